// round 15
// baseline (speedup 1.0000x reference)
#include <cuda_runtime.h>
#include <cstdint>

// Sparse ConvTranspose3d on GB300 (sm_103a) — mma.sync tf32 tensor cores.
//   out[r,:] = bias + sum_{(k,n): out_index[k,n]==r} feats[n,:] @ weight[k,:,:]^T
//
// R15 = R14 with:
//  - KCHUNK=3 (grid.y=9, 4230 blocks = 9.5 waves): wave-quantization tail
//    ~20% -> ~5%. W/feats re-reads are L2-resident.
//  - g_idx2 pre-pass packs (row<<1 | count==1): no dependent counts-gather in
//    the main loop, half the metadata loads.
//  - coalesced cond_bias_init (thread per float4).
//  A in registers (R14), fragment-major prepack (R12), cout perm (R11) kept.

#define CIN    64
#define COUT   64
#define TILE_N 128
#define KCHUNK 3
#define MAX_ROWS (60000 * 27)
#define N_PAD  60160                       // 470 * 128 >= N
#define NT128  (N_PAD / 128)

__device__ int   g_counts[MAX_ROWS];
__device__ int   g_idx2[MAX_ROWS];              // packed (row<<1)|iscnt1, [27,N]
__device__ float g_feats_f[N_PAD * CIN];        // fragment-major feats (tf32)
__device__ float g_weight_f[27 * COUT * CIN];   // fragment-major, cout-permuted

// ---------------------------------------------------------------- pre-pass ----
__global__ void zero_counts_kernel(int n4) {
    int i = blockIdx.x * blockDim.x + threadIdx.x;
    if (i < n4) reinterpret_cast<int4*>(g_counts)[i] = make_int4(0, 0, 0, 0);
}
__global__ void count_kernel(const int* __restrict__ oi, int total) {
    int i = blockIdx.x * blockDim.x + threadIdx.x;
    if (i < total) atomicAdd(&g_counts[oi[i]], 1);
}
// pack row id + (count==1) flag, in the same [k][n] layout as out_index
__global__ void prep_index_kernel(const int* __restrict__ oi, int total) {
    int i = blockIdx.x * blockDim.x + threadIdx.x;
    if (i < total) {
        int r = oi[i];
        g_idx2[i] = (r << 1) | (__ldg(&g_counts[r]) == 1 ? 1 : 0);
    }
}
// coalesced: one float4 per thread; rows with count!=1 get bias
__global__ void cond_bias_init_kernel(const float4* __restrict__ bias4,
                                      float4* __restrict__ out4, int tot4) {
    int i = blockIdx.x * blockDim.x + threadIdx.x;
    if (i >= tot4) return;
    int r = i >> 4;
    if (__ldg(&g_counts[r]) != 1) out4[i] = bias4[i & 15];
}

__device__ __forceinline__ uint32_t to_tf32(float f) {
    uint32_t u;
    asm("cvt.rna.tf32.f32 %0, %1;" : "=r"(u) : "f"(f));
    return u;
}

// feats -> fragment-major: slot i = (tile, mi, kc, lane); 4 floats
__global__ void prep_feats_kernel(const float* __restrict__ feats, int N, int tot) {
    int i = blockIdx.x * blockDim.x + threadIdx.x;
    if (i >= tot) return;                       // tot = NT128*2048
    int lane = i & 31;
    int kc   = (i >> 5) & 7;
    int mi   = (i >> 8) & 7;
    int tile = i >> 11;
    int g = lane >> 2, t = lane & 3;
    int r0 = tile * 128 + mi * 16 + g;
    int r1 = r0 + 8;
    int c0 = kc * 8 + t;
    float v0 = (r0 < N) ? feats[(size_t)r0 * CIN + c0]     : 0.f;
    float v1 = (r1 < N) ? feats[(size_t)r1 * CIN + c0]     : 0.f;
    float v2 = (r0 < N) ? feats[(size_t)r0 * CIN + c0 + 4] : 0.f;
    float v3 = (r1 < N) ? feats[(size_t)r1 * CIN + c0 + 4] : 0.f;
    uint4 o = make_uint4(to_tf32(v0), to_tf32(v1), to_tf32(v2), to_tf32(v3));
    reinterpret_cast<uint4*>(g_feats_f)[i] = o;
}

// weight -> fragment-major + cout permutation L(f) (see R11/R12)
__device__ __forceinline__ int Lperm(int f) {
    int nt = f >> 3, ct = f & 7;
    return 16 * (nt >> 1) + 2 * (nt & 1) + 4 * (ct >> 1) + (ct & 1);
}
__global__ void prep_weight_kernel(const float* __restrict__ w, int tot) {
    int i = blockIdx.x * blockDim.x + threadIdx.x;
    if (i >= tot) return;                       // tot = 27*1024
    int lane = i & 31;
    int m    = (i >> 5) & 3;
    int kc   = (i >> 7) & 7;
    int k    = i >> 10;
    int g = lane >> 2, t = lane & 3;
    int f0 = 8 * (2 * m)     + g;
    int f1 = 8 * (2 * m + 1) + g;
    const float* wk = w + (size_t)k * COUT * CIN;
    int c0 = kc * 8 + t;
    float v0 = wk[Lperm(f0) * CIN + c0];
    float v1 = wk[Lperm(f0) * CIN + c0 + 4];
    float v2 = wk[Lperm(f1) * CIN + c0];
    float v3 = wk[Lperm(f1) * CIN + c0 + 4];
    uint4 o = make_uint4(to_tf32(v0), to_tf32(v1), to_tf32(v2), to_tf32(v3));
    reinterpret_cast<uint4*>(g_weight_f)[i] = o;
}

// ---------------------------------------------------------------- helpers ----
__device__ __forceinline__ uint32_t f2u(float f) { return __float_as_uint(f); }

__device__ __forceinline__ void mma_tf32(float c[4], const uint32_t a[4],
                                         uint32_t b0, uint32_t b1) {
    asm volatile(
        "mma.sync.aligned.m16n8k8.row.col.f32.tf32.tf32.f32 "
        "{%0,%1,%2,%3}, {%4,%5,%6,%7}, {%8,%9}, {%0,%1,%2,%3};"
        : "+f"(c[0]), "+f"(c[1]), "+f"(c[2]), "+f"(c[3])
        : "r"(a[0]), "r"(a[1]), "r"(a[2]), "r"(a[3]), "r"(b0), "r"(b1));
}

__device__ __forceinline__ void cp16(float* smem_dst, const float* gsrc) {
    unsigned d = (unsigned)__cvta_generic_to_shared(smem_dst);
    asm volatile("cp.async.cg.shared.global [%0], [%1], 16;\n"
                 :: "r"(d), "l"(gsrc));
}

// ------------------------------------------------------------- main kernel ----
#define W_FLOATS 4096

__global__ void __launch_bounds__(128, 3) spconvt_mma_kernel(
    const float* __restrict__ bias,      // [64]
    float*       __restrict__ out,       // [n_out, 64]
    int N, int KV)
{
    extern __shared__ float smem[];
    float* Wb = smem;                        // 2 fragment-major W buffers

    const int tid  = threadIdx.x;
    const int w    = tid >> 5;
    const int lane = tid & 31;
    const int g    = lane >> 2;
    const int t    = lane & 3;
    const int n0   = blockIdx.x * TILE_N;
    const int k0   = blockIdx.y * KCHUNK;

    // ---- W[k] loader: straight 16KB async copy ----
    auto cpW = [&](int k, int b) {
        const float* src = g_weight_f + (size_t)k * W_FLOATS;
        float* dst = Wb + b * W_FLOATS;
        #pragma unroll
        for (int j = 0; j < 8; j++) {
            int idx = tid + 128 * j;
            cp16(dst + idx * 4, src + idx * 4);
        }
        asm volatile("cp.async.commit_group;\n");
    };
    cpW(k0, 0);

    // ---- A fragments: coalesced LDG.128 burst, resident in registers ----
    uint32_t areg[2][8][4];
    {
        const float4* asrc = reinterpret_cast<const float4*>(g_feats_f)
                           + (size_t)blockIdx.x * 2048;
        #pragma unroll
        for (int mt = 0; mt < 2; mt++) {
            int mi = 2 * w + mt;
            #pragma unroll
            for (int kc = 0; kc < 8; kc++) {
                float4 av = __ldg(&asrc[(mi * 8 + kc) * 32 + lane]);
                areg[mt][kc][0] = f2u(av.x); areg[mt][kc][1] = f2u(av.y);
                areg[mt][kc][2] = f2u(av.z); areg[mt][kc][3] = f2u(av.w);
            }
        }
    }

    // per-thread bias float4s: logical couts [16m+4t, +4) -> bias4[4m + t]
    float4 b4[4];
    #pragma unroll
    for (int m = 0; m < 4; m++)
        b4[m] = __ldg(reinterpret_cast<const float4*>(bias) + 4 * m + t);

    asm volatile("cp.async.wait_group 0;\n" ::: "memory");
    __syncthreads();

    const int p0 = 32 * w + g;                // first of 4 owned point rows
    int buf = 0;

    for (int kk = 0; kk < KCHUNK; kk++) {
        int k = k0 + kk;
        if (k >= KV) break;
        bool more = (kk + 1 < KCHUNK) && (k + 1 < KV);

        if (more) cpW(k + 1, buf ^ 1);

        // packed scatter metadata (row<<1 | cnt1)
        int rv[4];
        #pragma unroll
        for (int j = 0; j < 4; j++) {
            int n = n0 + p0 + 8 * j;
            rv[j] = (n < N) ? __ldg(&g_idx2[(size_t)k * N + n]) : -1;
        }

        const float* Wc = Wb + buf * W_FLOATS;

        float acc[2][8][4];
        #pragma unroll
        for (int mt = 0; mt < 2; mt++)
            #pragma unroll
            for (int nt = 0; nt < 8; nt++)
                #pragma unroll
                for (int x = 0; x < 4; x++) acc[mt][nt][x] = 0.f;

        #pragma unroll
        for (int kc = 0; kc < 8; kc++) {
            #pragma unroll
            for (int m = 0; m < 4; m++) {
                float4 bv = *reinterpret_cast<const float4*>(
                    Wc + ((kc * 4 + m) * 32 + lane) * 4);
                uint32_t b0a = f2u(bv.x), b1a = f2u(bv.y);   // nt = 2m
                uint32_t b0b = f2u(bv.z), b1b = f2u(bv.w);   // nt = 2m+1
                mma_tf32(acc[0][2 * m],     areg[0][kc], b0a, b1a);
                mma_tf32(acc[1][2 * m],     areg[1][kc], b0a, b1a);
                mma_tf32(acc[0][2 * m + 1], areg[0][kc], b0b, b1b);
                mma_tf32(acc[1][2 * m + 1], areg[1][kc], b0b, b1b);
            }
        }

        // ---- scatter epilogue ----
        #pragma unroll
        for (int j = 0; j < 4; j++) {
            if (rv[j] < 0) continue;
            const int mt = j >> 1, hi = (j & 1) * 2;
            float* dst = out + (size_t)(rv[j] >> 1) * COUT + 4 * t;
            if (rv[j] & 1) {
                #pragma unroll
                for (int m = 0; m < 4; m++) {
                    float4 v = make_float4(acc[mt][2*m][hi]       + b4[m].x,
                                           acc[mt][2*m][hi + 1]   + b4[m].y,
                                           acc[mt][2*m+1][hi]     + b4[m].z,
                                           acc[mt][2*m+1][hi + 1] + b4[m].w);
                    *reinterpret_cast<float4*>(dst + 16 * m) = v;
                }
            } else {
                #pragma unroll
                for (int m = 0; m < 4; m++) {
                    asm volatile("red.global.add.v4.f32 [%0], {%1, %2, %3, %4};"
                                 :: "l"(dst + 16 * m),
                                    "f"(acc[mt][2*m][hi]),
                                    "f"(acc[mt][2*m][hi + 1]),
                                    "f"(acc[mt][2*m+1][hi]),
                                    "f"(acc[mt][2*m+1][hi + 1])
                                 : "memory");
                }
            }
        }

        asm volatile("cp.async.wait_group 0;\n" ::: "memory");
        __syncthreads();
        buf ^= 1;
    }
}

extern "C" void kernel_launch(void* const* d_in, const int* in_sizes, int n_in,
                              void* d_out, int out_size) {
    const float* feats     = (const float*)d_in[0];   // [N, 64]
    const float* weight    = (const float*)d_in[1];   // [27, 64, 64]
    const float* bias      = (const float*)d_in[2];   // [64]
    const int*   out_index = (const int*)d_in[3];     // [27, N]
    float* out = (float*)d_out;                        // [n_out, 64]

    int N  = in_sizes[0] / CIN;
    int KV = in_sizes[1] / (COUT * CIN);
    int n_out = out_size / COUT;
    int total_idx = in_sizes[3];                       // KV * N

    int z4 = (n_out + 3) / 4;
    zero_counts_kernel<<<(z4 + 255) / 256, 256>>>(z4);
    count_kernel<<<(total_idx + 255) / 256, 256>>>(out_index, total_idx);
    prep_index_kernel<<<(total_idx + 255) / 256, 256>>>(out_index, total_idx);
    int tot4 = out_size / 4;
    cond_bias_init_kernel<<<(tot4 + 255) / 256, 256>>>(
        (const float4*)bias, (float4*)out, tot4);

    // fragment-major prepack
    int tot_a = NT128 * 2048;
    prep_feats_kernel<<<(tot_a + 255) / 256, 256>>>(feats, N, tot_a);
    int tot_w = KV * 1024;
    prep_weight_kernel<<<(tot_w + 255) / 256, 256>>>(weight, tot_w);

    const int smem_bytes = 2 * W_FLOATS * sizeof(float);   // 32KB
    cudaFuncSetAttribute(spconvt_mma_kernel,
                         cudaFuncAttributeMaxDynamicSharedMemorySize, smem_bytes);
    dim3 grid((N + TILE_N - 1) / TILE_N, (KV + KCHUNK - 1) / KCHUNK);
    spconvt_mma_kernel<<<grid, 128, smem_bytes>>>(bias, out, N, KV);
}

// round 16
// speedup vs baseline: 1.2341x; 1.2341x over previous
#include <cuda_runtime.h>
#include <cstdint>

// Sparse ConvTranspose3d on GB300 (sm_103a) — mma.sync tf32 tensor cores.
//   out[r,:] = bias + sum_{(k,n): out_index[k,n]==r} feats[n,:] @ weight[k,:,:]^T
//
// R16: PERSISTENT BALANCED BLOCKS — grid = 456 (152 SM x 3 via launch_bounds),
// exactly one wave. Each block walks a contiguous range of the 12663 (tile,k)
// units (27-28 each, tile-major). A fragments live in registers, reloaded only
// at tile boundaries (~2x per block). W double-buffered via cp.async per unit.
// Packed g_idx2 metadata (row<<1|cnt1). Grid-stride cond_bias_init (fixes the
// 61.5us block-churn regression of R15).

#define CIN    64
#define COUT   64
#define TILE_N 128
#define MAX_ROWS (60000 * 27)
#define N_PAD  60160                       // 470 * 128 >= N
#define NT128  (N_PAD / 128)
#define GRID_MAIN 456                      // 152 SMs * 3 blocks
#define W_FLOATS 4096

__device__ int   g_counts[MAX_ROWS];
__device__ int   g_idx2[MAX_ROWS];              // packed (row<<1)|iscnt1, [27,N]
__device__ float g_feats_f[N_PAD * CIN];        // fragment-major feats (tf32)
__device__ float g_weight_f[27 * COUT * CIN];   // fragment-major, cout-permuted

// ---------------------------------------------------------------- pre-pass ----
__global__ void zero_counts_kernel(int n4) {
    int i = blockIdx.x * blockDim.x + threadIdx.x;
    if (i < n4) reinterpret_cast<int4*>(g_counts)[i] = make_int4(0, 0, 0, 0);
}
__global__ void count_kernel(const int* __restrict__ oi, int total) {
    int i = blockIdx.x * blockDim.x + threadIdx.x;
    if (i < total) atomicAdd(&g_counts[oi[i]], 1);
}
__global__ void prep_index_kernel(const int* __restrict__ oi, int total) {
    int i = blockIdx.x * blockDim.x + threadIdx.x;
    if (i < total) {
        int r = oi[i];
        g_idx2[i] = (r << 1) | (__ldg(&g_counts[r]) == 1 ? 1 : 0);
    }
}
// grid-stride, coalesced: rows with count!=1 get bias
__global__ void cond_bias_init_kernel(const float4* __restrict__ bias4,
                                      float4* __restrict__ out4, int tot4) {
    int stride = gridDim.x * blockDim.x;
    for (int i = blockIdx.x * blockDim.x + threadIdx.x; i < tot4; i += stride) {
        if (__ldg(&g_counts[i >> 4]) != 1) out4[i] = bias4[i & 15];
    }
}

__device__ __forceinline__ uint32_t to_tf32(float f) {
    uint32_t u;
    asm("cvt.rna.tf32.f32 %0, %1;" : "=r"(u) : "f"(f));
    return u;
}

// feats -> fragment-major: slot i = (tile, mi, kc, lane); 4 floats
__global__ void prep_feats_kernel(const float* __restrict__ feats, int N, int tot) {
    int i = blockIdx.x * blockDim.x + threadIdx.x;
    if (i >= tot) return;                       // tot = NT128*2048
    int lane = i & 31;
    int kc   = (i >> 5) & 7;
    int mi   = (i >> 8) & 7;
    int tile = i >> 11;
    int g = lane >> 2, t = lane & 3;
    int r0 = tile * 128 + mi * 16 + g;
    int r1 = r0 + 8;
    int c0 = kc * 8 + t;
    float v0 = (r0 < N) ? feats[(size_t)r0 * CIN + c0]     : 0.f;
    float v1 = (r1 < N) ? feats[(size_t)r1 * CIN + c0]     : 0.f;
    float v2 = (r0 < N) ? feats[(size_t)r0 * CIN + c0 + 4] : 0.f;
    float v3 = (r1 < N) ? feats[(size_t)r1 * CIN + c0 + 4] : 0.f;
    uint4 o = make_uint4(to_tf32(v0), to_tf32(v1), to_tf32(v2), to_tf32(v3));
    reinterpret_cast<uint4*>(g_feats_f)[i] = o;
}

// weight -> fragment-major + cout permutation L(f) (see R11/R12)
__device__ __forceinline__ int Lperm(int f) {
    int nt = f >> 3, ct = f & 7;
    return 16 * (nt >> 1) + 2 * (nt & 1) + 4 * (ct >> 1) + (ct & 1);
}
__global__ void prep_weight_kernel(const float* __restrict__ w, int tot) {
    int i = blockIdx.x * blockDim.x + threadIdx.x;
    if (i >= tot) return;                       // tot = 27*1024
    int lane = i & 31;
    int m    = (i >> 5) & 3;
    int kc   = (i >> 7) & 7;
    int k    = i >> 10;
    int g = lane >> 2, t = lane & 3;
    int f0 = 8 * (2 * m)     + g;
    int f1 = 8 * (2 * m + 1) + g;
    const float* wk = w + (size_t)k * COUT * CIN;
    int c0 = kc * 8 + t;
    float v0 = wk[Lperm(f0) * CIN + c0];
    float v1 = wk[Lperm(f0) * CIN + c0 + 4];
    float v2 = wk[Lperm(f1) * CIN + c0];
    float v3 = wk[Lperm(f1) * CIN + c0 + 4];
    uint4 o = make_uint4(to_tf32(v0), to_tf32(v1), to_tf32(v2), to_tf32(v3));
    reinterpret_cast<uint4*>(g_weight_f)[i] = o;
}

// ---------------------------------------------------------------- helpers ----
__device__ __forceinline__ uint32_t f2u(float f) { return __float_as_uint(f); }

__device__ __forceinline__ void mma_tf32(float c[4], const uint32_t a[4],
                                         uint32_t b0, uint32_t b1) {
    asm volatile(
        "mma.sync.aligned.m16n8k8.row.col.f32.tf32.tf32.f32 "
        "{%0,%1,%2,%3}, {%4,%5,%6,%7}, {%8,%9}, {%0,%1,%2,%3};"
        : "+f"(c[0]), "+f"(c[1]), "+f"(c[2]), "+f"(c[3])
        : "r"(a[0]), "r"(a[1]), "r"(a[2]), "r"(a[3]), "r"(b0), "r"(b1));
}

__device__ __forceinline__ void cp16(float* smem_dst, const float* gsrc) {
    unsigned d = (unsigned)__cvta_generic_to_shared(smem_dst);
    asm volatile("cp.async.cg.shared.global [%0], [%1], 16;\n"
                 :: "r"(d), "l"(gsrc));
}

// ------------------------------------------------------------- main kernel ----
__global__ void __launch_bounds__(128, 3) spconvt_mma_kernel(
    const float* __restrict__ bias,      // [64]
    float*       __restrict__ out,       // [n_out, 64]
    int N, int KV, int units)            // units = ntiles * KV
{
    extern __shared__ float smem[];
    float* Wb = smem;                        // 2 fragment-major W buffers

    const int tid  = threadIdx.x;
    const int w    = tid >> 5;
    const int lane = tid & 31;
    const int g    = lane >> 2;
    const int t    = lane & 3;

    // balanced contiguous unit range for this block
    const int nb   = gridDim.x;
    const int base = units / nb, rem = units % nb;
    const int b    = blockIdx.x;
    const int u0   = b * base + (b < rem ? b : rem);
    const int u1   = u0 + base + (b < rem ? 1 : 0);
    if (u0 >= u1) return;

    // ---- W loader ----
    auto cpW = [&](int k, int bf) {
        const float* src = g_weight_f + (size_t)k * W_FLOATS;
        float* dst = Wb + bf * W_FLOATS;
        #pragma unroll
        for (int j = 0; j < 8; j++) {
            int idx = tid + 128 * j;
            cp16(dst + idx * 4, src + idx * 4);
        }
        asm volatile("cp.async.commit_group;\n");
    };

    // ---- A fragment loader (registers), per tile ----
    uint32_t areg[2][8][4];
    auto loadA = [&](int tile) {
        const float4* asrc = reinterpret_cast<const float4*>(g_feats_f)
                           + (size_t)tile * 2048;
        #pragma unroll
        for (int mt = 0; mt < 2; mt++) {
            int mi = 2 * w + mt;
            #pragma unroll
            for (int kc = 0; kc < 8; kc++) {
                float4 av = __ldg(&asrc[(mi * 8 + kc) * 32 + lane]);
                areg[mt][kc][0] = f2u(av.x); areg[mt][kc][1] = f2u(av.y);
                areg[mt][kc][2] = f2u(av.z); areg[mt][kc][3] = f2u(av.w);
            }
        }
    };

    int tile = u0 / KV;
    int k    = u0 - tile * KV;

    cpW(k, 0);
    loadA(tile);

    float4 b4[4];
    #pragma unroll
    for (int m = 0; m < 4; m++)
        b4[m] = __ldg(reinterpret_cast<const float4*>(bias) + 4 * m + t);

    asm volatile("cp.async.wait_group 0;\n" ::: "memory");
    __syncthreads();

    const int pg = 32 * w + g;               // first owned point row (rel. tile)
    int buf = 0;

    for (int u = u0; u < u1; u++) {
        // next unit coords; prefetch its W
        int ntile = tile, nk = k + 1;
        if (nk == KV) { nk = 0; ntile++; }
        if (u + 1 < u1) cpW(nk, buf ^ 1);

        // packed scatter metadata
        const int n0 = tile * TILE_N;
        int rv[4];
        #pragma unroll
        for (int j = 0; j < 4; j++) {
            int n = n0 + pg + 8 * j;
            rv[j] = (n < N) ? __ldg(&g_idx2[(size_t)k * N + n]) : -1;
        }

        const float* Wc = Wb + buf * W_FLOATS;

        float acc[2][8][4];
        #pragma unroll
        for (int mt = 0; mt < 2; mt++)
            #pragma unroll
            for (int nt = 0; nt < 8; nt++)
                #pragma unroll
                for (int x = 0; x < 4; x++) acc[mt][nt][x] = 0.f;

        #pragma unroll
        for (int kc = 0; kc < 8; kc++) {
            #pragma unroll
            for (int m = 0; m < 4; m++) {
                float4 bv = *reinterpret_cast<const float4*>(
                    Wc + ((kc * 4 + m) * 32 + lane) * 4);
                uint32_t b0a = f2u(bv.x), b1a = f2u(bv.y);   // nt = 2m
                uint32_t b0b = f2u(bv.z), b1b = f2u(bv.w);   // nt = 2m+1
                mma_tf32(acc[0][2 * m],     areg[0][kc], b0a, b1a);
                mma_tf32(acc[1][2 * m],     areg[1][kc], b0a, b1a);
                mma_tf32(acc[0][2 * m + 1], areg[0][kc], b0b, b1b);
                mma_tf32(acc[1][2 * m + 1], areg[1][kc], b0b, b1b);
            }
        }

        // ---- scatter epilogue ----
        #pragma unroll
        for (int j = 0; j < 4; j++) {
            if (rv[j] < 0) continue;
            const int mt = j >> 1, hi = (j & 1) * 2;
            float* dst = out + (size_t)(rv[j] >> 1) * COUT + 4 * t;
            if (rv[j] & 1) {
                #pragma unroll
                for (int m = 0; m < 4; m++) {
                    float4 v = make_float4(acc[mt][2*m][hi]       + b4[m].x,
                                           acc[mt][2*m][hi + 1]   + b4[m].y,
                                           acc[mt][2*m+1][hi]     + b4[m].z,
                                           acc[mt][2*m+1][hi + 1] + b4[m].w);
                    *reinterpret_cast<float4*>(dst + 16 * m) = v;
                }
            } else {
                #pragma unroll
                for (int m = 0; m < 4; m++) {
                    asm volatile("red.global.add.v4.f32 [%0], {%1, %2, %3, %4};"
                                 :: "l"(dst + 16 * m),
                                    "f"(acc[mt][2*m][hi]),
                                    "f"(acc[mt][2*m][hi + 1]),
                                    "f"(acc[mt][2*m+1][hi]),
                                    "f"(acc[mt][2*m+1][hi + 1])
                                 : "memory");
                }
            }
        }

        asm volatile("cp.async.wait_group 0;\n" ::: "memory");
        __syncthreads();
        buf ^= 1;

        // advance; reload A registers on tile boundary (rare)
        if (ntile != tile && u + 1 < u1) loadA(ntile);
        tile = ntile; k = nk;
    }
}

extern "C" void kernel_launch(void* const* d_in, const int* in_sizes, int n_in,
                              void* d_out, int out_size) {
    const float* feats     = (const float*)d_in[0];   // [N, 64]
    const float* weight    = (const float*)d_in[1];   // [27, 64, 64]
    const float* bias      = (const float*)d_in[2];   // [64]
    const int*   out_index = (const int*)d_in[3];     // [27, N]
    float* out = (float*)d_out;                        // [n_out, 64]

    int N  = in_sizes[0] / CIN;
    int KV = in_sizes[1] / (COUT * CIN);
    int n_out = out_size / COUT;
    int total_idx = in_sizes[3];                       // KV * N

    int z4 = (n_out + 3) / 4;
    zero_counts_kernel<<<(z4 + 255) / 256, 256>>>(z4);
    count_kernel<<<(total_idx + 255) / 256, 256>>>(out_index, total_idx);
    prep_index_kernel<<<(total_idx + 255) / 256, 256>>>(out_index, total_idx);
    int tot4 = out_size / 4;
    cond_bias_init_kernel<<<1824, 256>>>((const float4*)bias, (float4*)out, tot4);

    // fragment-major prepack
    int tot_a = NT128 * 2048;
    prep_feats_kernel<<<(tot_a + 255) / 256, 256>>>(feats, N, tot_a);
    int tot_w = KV * 1024;
    prep_weight_kernel<<<(tot_w + 255) / 256, 256>>>(weight, tot_w);

    // persistent balanced main kernel: one wave of 456 blocks
    int ntiles = (N + TILE_N - 1) / TILE_N;
    int units  = ntiles * KV;
    const int smem_bytes = 2 * W_FLOATS * sizeof(float);   // 32KB
    cudaFuncSetAttribute(spconvt_mma_kernel,
                         cudaFuncAttributeMaxDynamicSharedMemorySize, smem_bytes);
    spconvt_mma_kernel<<<GRID_MAIN, 128, smem_bytes>>>(bias, out, N, KV, units);
}

// round 17
// speedup vs baseline: 1.2558x; 1.0175x over previous
#include <cuda_runtime.h>
#include <cstdint>

// Sparse ConvTranspose3d on GB300 (sm_103a) — mma.sync tf32 tensor cores.
//   out[r,:] = bias + sum_{(k,n): out_index[k,n]==r} feats[n,:] @ weight[k,:,:]^T
//
// R17 = R16 (persistent balanced blocks, A-in-regs, fragment prepack, cout perm,
// packed idx metadata) + COMPACT-LIST BIAS INIT:
//   The old cond_bias_init scanned all 25.9M output float4s (55us at 1.5% DRAM
//   — pure loop overhead). Now: a row-scan appends count!=1 rows (~5%) to a
//   compact list; a list-driven kernel writes bias only to those rows.

#define CIN    64
#define COUT   64
#define TILE_N 128
#define MAX_ROWS (60000 * 27)
#define N_PAD  60160                       // 470 * 128 >= N
#define NT128  (N_PAD / 128)
#define GRID_MAIN 456                      // 152 SMs * 3 blocks
#define W_FLOATS 4096

__device__ int   g_counts[MAX_ROWS];
__device__ int   g_idx2[MAX_ROWS];              // packed (row<<1)|iscnt1, [27,N]
__device__ int   g_fix_rows[MAX_ROWS];          // rows needing bias init
__device__ int   g_fix_cnt;
__device__ float g_feats_f[N_PAD * CIN];        // fragment-major feats (tf32)
__device__ float g_weight_f[27 * COUT * CIN];   // fragment-major, cout-permuted

// ---------------------------------------------------------------- pre-pass ----
__global__ void zero_counts_kernel(int n4) {
    int i = blockIdx.x * blockDim.x + threadIdx.x;
    if (i == 0) g_fix_cnt = 0;
    if (i < n4) reinterpret_cast<int4*>(g_counts)[i] = make_int4(0, 0, 0, 0);
}
__global__ void count_kernel(const int* __restrict__ oi, int total) {
    int i = blockIdx.x * blockDim.x + threadIdx.x;
    if (i < total) atomicAdd(&g_counts[oi[i]], 1);
}
__global__ void prep_index_kernel(const int* __restrict__ oi, int total) {
    int i = blockIdx.x * blockDim.x + threadIdx.x;
    if (i < total) {
        int r = oi[i];
        g_idx2[i] = (r << 1) | (__ldg(&g_counts[r]) == 1 ? 1 : 0);
    }
}
// scan rows, append count!=1 rows to compact list
__global__ void scan_rows_kernel(int n_out) {
    int r = blockIdx.x * blockDim.x + threadIdx.x;
    if (r < n_out && __ldg(&g_counts[r]) != 1) {
        int pos = atomicAdd(&g_fix_cnt, 1);
        g_fix_rows[pos] = r;
    }
}
// init only listed rows: 16 lanes cooperate per row (coalesced 256B bursts)
__global__ void fix_bias_init_kernel(const float4* __restrict__ bias4,
                                     float4* __restrict__ out4) {
    int total = g_fix_cnt * 16;
    int stride = gridDim.x * blockDim.x;
    for (int j = blockIdx.x * blockDim.x + threadIdx.x; j < total; j += stride) {
        int row = g_fix_rows[j >> 4];
        out4[(size_t)row * 16 + (j & 15)] = bias4[j & 15];
    }
}

__device__ __forceinline__ uint32_t to_tf32(float f) {
    uint32_t u;
    asm("cvt.rna.tf32.f32 %0, %1;" : "=r"(u) : "f"(f));
    return u;
}

// feats -> fragment-major: slot i = (tile, mi, kc, lane); 4 floats
__global__ void prep_feats_kernel(const float* __restrict__ feats, int N, int tot) {
    int i = blockIdx.x * blockDim.x + threadIdx.x;
    if (i >= tot) return;                       // tot = NT128*2048
    int lane = i & 31;
    int kc   = (i >> 5) & 7;
    int mi   = (i >> 8) & 7;
    int tile = i >> 11;
    int g = lane >> 2, t = lane & 3;
    int r0 = tile * 128 + mi * 16 + g;
    int r1 = r0 + 8;
    int c0 = kc * 8 + t;
    float v0 = (r0 < N) ? feats[(size_t)r0 * CIN + c0]     : 0.f;
    float v1 = (r1 < N) ? feats[(size_t)r1 * CIN + c0]     : 0.f;
    float v2 = (r0 < N) ? feats[(size_t)r0 * CIN + c0 + 4] : 0.f;
    float v3 = (r1 < N) ? feats[(size_t)r1 * CIN + c0 + 4] : 0.f;
    uint4 o = make_uint4(to_tf32(v0), to_tf32(v1), to_tf32(v2), to_tf32(v3));
    reinterpret_cast<uint4*>(g_feats_f)[i] = o;
}

// weight -> fragment-major + cout permutation L(f) (see R11/R12)
__device__ __forceinline__ int Lperm(int f) {
    int nt = f >> 3, ct = f & 7;
    return 16 * (nt >> 1) + 2 * (nt & 1) + 4 * (ct >> 1) + (ct & 1);
}
__global__ void prep_weight_kernel(const float* __restrict__ w, int tot) {
    int i = blockIdx.x * blockDim.x + threadIdx.x;
    if (i >= tot) return;                       // tot = 27*1024
    int lane = i & 31;
    int m    = (i >> 5) & 3;
    int kc   = (i >> 7) & 7;
    int k    = i >> 10;
    int g = lane >> 2, t = lane & 3;
    int f0 = 8 * (2 * m)     + g;
    int f1 = 8 * (2 * m + 1) + g;
    const float* wk = w + (size_t)k * COUT * CIN;
    int c0 = kc * 8 + t;
    float v0 = wk[Lperm(f0) * CIN + c0];
    float v1 = wk[Lperm(f0) * CIN + c0 + 4];
    float v2 = wk[Lperm(f1) * CIN + c0];
    float v3 = wk[Lperm(f1) * CIN + c0 + 4];
    uint4 o = make_uint4(to_tf32(v0), to_tf32(v1), to_tf32(v2), to_tf32(v3));
    reinterpret_cast<uint4*>(g_weight_f)[i] = o;
}

// ---------------------------------------------------------------- helpers ----
__device__ __forceinline__ uint32_t f2u(float f) { return __float_as_uint(f); }

__device__ __forceinline__ void mma_tf32(float c[4], const uint32_t a[4],
                                         uint32_t b0, uint32_t b1) {
    asm volatile(
        "mma.sync.aligned.m16n8k8.row.col.f32.tf32.tf32.f32 "
        "{%0,%1,%2,%3}, {%4,%5,%6,%7}, {%8,%9}, {%0,%1,%2,%3};"
        : "+f"(c[0]), "+f"(c[1]), "+f"(c[2]), "+f"(c[3])
        : "r"(a[0]), "r"(a[1]), "r"(a[2]), "r"(a[3]), "r"(b0), "r"(b1));
}

__device__ __forceinline__ void cp16(float* smem_dst, const float* gsrc) {
    unsigned d = (unsigned)__cvta_generic_to_shared(smem_dst);
    asm volatile("cp.async.cg.shared.global [%0], [%1], 16;\n"
                 :: "r"(d), "l"(gsrc));
}

// ------------------------------------------------------------- main kernel ----
__global__ void __launch_bounds__(128, 3) spconvt_mma_kernel(
    const float* __restrict__ bias,      // [64]
    float*       __restrict__ out,       // [n_out, 64]
    int N, int KV, int units)            // units = ntiles * KV
{
    extern __shared__ float smem[];
    float* Wb = smem;                        // 2 fragment-major W buffers

    const int tid  = threadIdx.x;
    const int w    = tid >> 5;
    const int lane = tid & 31;
    const int g    = lane >> 2;
    const int t    = lane & 3;

    // balanced contiguous unit range for this block
    const int nb   = gridDim.x;
    const int base = units / nb, rem = units % nb;
    const int b    = blockIdx.x;
    const int u0   = b * base + (b < rem ? b : rem);
    const int u1   = u0 + base + (b < rem ? 1 : 0);
    if (u0 >= u1) return;

    auto cpW = [&](int k, int bf) {
        const float* src = g_weight_f + (size_t)k * W_FLOATS;
        float* dst = Wb + bf * W_FLOATS;
        #pragma unroll
        for (int j = 0; j < 8; j++) {
            int idx = tid + 128 * j;
            cp16(dst + idx * 4, src + idx * 4);
        }
        asm volatile("cp.async.commit_group;\n");
    };

    uint32_t areg[2][8][4];
    auto loadA = [&](int tile) {
        const float4* asrc = reinterpret_cast<const float4*>(g_feats_f)
                           + (size_t)tile * 2048;
        #pragma unroll
        for (int mt = 0; mt < 2; mt++) {
            int mi = 2 * w + mt;
            #pragma unroll
            for (int kc = 0; kc < 8; kc++) {
                float4 av = __ldg(&asrc[(mi * 8 + kc) * 32 + lane]);
                areg[mt][kc][0] = f2u(av.x); areg[mt][kc][1] = f2u(av.y);
                areg[mt][kc][2] = f2u(av.z); areg[mt][kc][3] = f2u(av.w);
            }
        }
    };

    int tile = u0 / KV;
    int k    = u0 - tile * KV;

    cpW(k, 0);
    loadA(tile);

    float4 b4[4];
    #pragma unroll
    for (int m = 0; m < 4; m++)
        b4[m] = __ldg(reinterpret_cast<const float4*>(bias) + 4 * m + t);

    asm volatile("cp.async.wait_group 0;\n" ::: "memory");
    __syncthreads();

    const int pg = 32 * w + g;               // first owned point row (rel. tile)
    int buf = 0;

    for (int u = u0; u < u1; u++) {
        int ntile = tile, nk = k + 1;
        if (nk == KV) { nk = 0; ntile++; }
        if (u + 1 < u1) cpW(nk, buf ^ 1);

        const int n0 = tile * TILE_N;
        int rv[4];
        #pragma unroll
        for (int j = 0; j < 4; j++) {
            int n = n0 + pg + 8 * j;
            rv[j] = (n < N) ? __ldg(&g_idx2[(size_t)k * N + n]) : -1;
        }

        const float* Wc = Wb + buf * W_FLOATS;

        float acc[2][8][4];
        #pragma unroll
        for (int mt = 0; mt < 2; mt++)
            #pragma unroll
            for (int nt = 0; nt < 8; nt++)
                #pragma unroll
                for (int x = 0; x < 4; x++) acc[mt][nt][x] = 0.f;

        #pragma unroll
        for (int kc = 0; kc < 8; kc++) {
            #pragma unroll
            for (int m = 0; m < 4; m++) {
                float4 bv = *reinterpret_cast<const float4*>(
                    Wc + ((kc * 4 + m) * 32 + lane) * 4);
                uint32_t b0a = f2u(bv.x), b1a = f2u(bv.y);   // nt = 2m
                uint32_t b0b = f2u(bv.z), b1b = f2u(bv.w);   // nt = 2m+1
                mma_tf32(acc[0][2 * m],     areg[0][kc], b0a, b1a);
                mma_tf32(acc[1][2 * m],     areg[1][kc], b0a, b1a);
                mma_tf32(acc[0][2 * m + 1], areg[0][kc], b0b, b1b);
                mma_tf32(acc[1][2 * m + 1], areg[1][kc], b0b, b1b);
            }
        }

        #pragma unroll
        for (int j = 0; j < 4; j++) {
            if (rv[j] < 0) continue;
            const int mt = j >> 1, hi = (j & 1) * 2;
            float* dst = out + (size_t)(rv[j] >> 1) * COUT + 4 * t;
            if (rv[j] & 1) {
                #pragma unroll
                for (int m = 0; m < 4; m++) {
                    float4 v = make_float4(acc[mt][2*m][hi]       + b4[m].x,
                                           acc[mt][2*m][hi + 1]   + b4[m].y,
                                           acc[mt][2*m+1][hi]     + b4[m].z,
                                           acc[mt][2*m+1][hi + 1] + b4[m].w);
                    *reinterpret_cast<float4*>(dst + 16 * m) = v;
                }
            } else {
                #pragma unroll
                for (int m = 0; m < 4; m++) {
                    asm volatile("red.global.add.v4.f32 [%0], {%1, %2, %3, %4};"
                                 :: "l"(dst + 16 * m),
                                    "f"(acc[mt][2*m][hi]),
                                    "f"(acc[mt][2*m][hi + 1]),
                                    "f"(acc[mt][2*m+1][hi]),
                                    "f"(acc[mt][2*m+1][hi + 1])
                                 : "memory");
                }
            }
        }

        asm volatile("cp.async.wait_group 0;\n" ::: "memory");
        __syncthreads();
        buf ^= 1;

        if (ntile != tile && u + 1 < u1) loadA(ntile);
        tile = ntile; k = nk;
    }
}

extern "C" void kernel_launch(void* const* d_in, const int* in_sizes, int n_in,
                              void* d_out, int out_size) {
    const float* feats     = (const float*)d_in[0];   // [N, 64]
    const float* weight    = (const float*)d_in[1];   // [27, 64, 64]
    const float* bias      = (const float*)d_in[2];   // [64]
    const int*   out_index = (const int*)d_in[3];     // [27, N]
    float* out = (float*)d_out;                        // [n_out, 64]

    int N  = in_sizes[0] / CIN;
    int KV = in_sizes[1] / (COUT * CIN);
    int n_out = out_size / COUT;
    int total_idx = in_sizes[3];                       // KV * N

    int z4 = (n_out + 3) / 4;
    zero_counts_kernel<<<(z4 + 255) / 256, 256>>>(z4);
    count_kernel<<<(total_idx + 255) / 256, 256>>>(out_index, total_idx);
    prep_index_kernel<<<(total_idx + 255) / 256, 256>>>(out_index, total_idx);
    scan_rows_kernel<<<(n_out + 255) / 256, 256>>>(n_out);
    fix_bias_init_kernel<<<1024, 256>>>((const float4*)bias, (float4*)out);

    // fragment-major prepack
    int tot_a = NT128 * 2048;
    prep_feats_kernel<<<(tot_a + 255) / 256, 256>>>(feats, N, tot_a);
    int tot_w = KV * 1024;
    prep_weight_kernel<<<(tot_w + 255) / 256, 256>>>(weight, tot_w);

    // persistent balanced main kernel: one wave of 456 blocks
    int ntiles = (N + TILE_N - 1) / TILE_N;
    int units  = ntiles * KV;
    const int smem_bytes = 2 * W_FLOATS * sizeof(float);   // 32KB
    cudaFuncSetAttribute(spconvt_mma_kernel,
                         cudaFuncAttributeMaxDynamicSharedMemorySize, smem_bytes);
    spconvt_mma_kernel<<<GRID_MAIN, 128, smem_bytes>>>(bias, out, N, KV, units);
}